// round 4
// baseline (speedup 1.0000x reference)
#include <cuda_runtime.h>

#define B_ 2
#define T_ 2048
#define H_ 16
#define D_ 64
#define C_ 1024

// ---------------- scratch (no cudaMalloc allowed) ----------------
__device__ float g_q[(size_t)B_ * H_ * T_ * D_];       // [B,H,T,D]
__device__ float g_k[(size_t)B_ * H_ * T_ * D_];
__device__ float g_v[(size_t)B_ * H_ * T_ * D_];
__device__ float g_y[(size_t)B_ * T_ * C_];            // attention out [B,T,C]
__device__ float g_W[H_ * T_];                          // mask weight table [H][rel]

// ---------------- packed f32x2 helpers ----------------
typedef unsigned long long ull;

__device__ __forceinline__ ull dup2(float x) {
    ull r;
    asm("mov.b64 %0, {%1, %1};" : "=l"(r) : "f"(x));
    return r;
}
__device__ __forceinline__ void fma2(ull& d, ull a, ull b) {
    asm("fma.rn.f32x2 %0, %1, %2, %0;" : "+l"(d) : "l"(a), "l"(b));
}
__device__ __forceinline__ void mul2(ull& d, ull a, ull b) {
    asm("mul.rn.f32x2 %0, %1, %2;" : "=l"(d) : "l"(a), "l"(b));
}
__device__ __forceinline__ float2 unpack2(ull v) {
    float2 f;
    f.x = __uint_as_float((unsigned)v);
    f.y = __uint_as_float((unsigned)(v >> 32));
    return f;
}

// bank-conflict swizzle: XOR the minor index (4-float granular, keeps 16B align)
__device__ __forceinline__ int sw4(int major) { return ((major >> 2) & 7) << 2; }

// ---------------- GEMM: C[M,N] = A[M,K] @ B[K,N] + bias[N] ----------------
// 128x128 tile, BK=8, 256 threads, 8x8 microtile, f32x2 packed FMA,
// 2-stage smem double buffering (one barrier per k-step).
// QKV=true: scatter output into g_q/g_k/g_v as [B,H,T,D] (N=3072 layout).
template<bool QKV>
__global__ __launch_bounds__(256, 2)
void gemm_bias_kernel(const float* __restrict__ A, const float* __restrict__ Bm,
                      const float* __restrict__ bias, float* __restrict__ C,
                      int M, int N, int K) {
    __shared__ float As[2][8][132];   // [stage][k][m] transposed, padded
    __shared__ float Bs[2][8][128];   // [stage][k][n]
    const int tid = threadIdx.x;
    const int tx = tid & 15, ty = tid >> 4;
    const int bm = blockIdx.y * 128, bn = blockIdx.x * 128;
    const int arow = tid >> 1, acol = (tid & 1) * 4;
    const int brow = tid >> 5, bcol = (tid & 31) * 4;

    ull acc[8][4];
#pragma unroll
    for (int i = 0; i < 8; i++)
#pragma unroll
        for (int j = 0; j < 4; j++) acc[i][j] = 0ull;

    const float* aptr = A + (size_t)(bm + arow) * K + acol;
    const float* bptr = Bm + (size_t)brow * N + bn + bcol;

    float4 av = *(const float4*)(aptr);
    float4 bv = *(const float4*)(bptr);
    As[0][acol + 0][arow] = av.x;
    As[0][acol + 1][arow] = av.y;
    As[0][acol + 2][arow] = av.z;
    As[0][acol + 3][arow] = av.w;
    *(float4*)&Bs[0][brow][bcol] = bv;
    __syncthreads();

    int stage = 0;
    for (int k0 = 0; k0 < K; k0 += 8) {
        const bool hasNext = (k0 + 8) < K;
        if (hasNext) {
            av = *(const float4*)(aptr + k0 + 8);
            bv = *(const float4*)(bptr + (size_t)(k0 + 8) * N);
        }
#pragma unroll
        for (int kk = 0; kk < 8; kk++) {
            float a[8];
            *(float4*)&a[0] = *(const float4*)&As[stage][kk][8 * ty];
            *(float4*)&a[4] = *(const float4*)&As[stage][kk][8 * ty + 4];
            ull b2[4];
            ulonglong2 bl0 = *(const ulonglong2*)&Bs[stage][kk][8 * tx];
            ulonglong2 bl1 = *(const ulonglong2*)&Bs[stage][kk][8 * tx + 4];
            b2[0] = bl0.x; b2[1] = bl0.y; b2[2] = bl1.x; b2[3] = bl1.y;
#pragma unroll
            for (int i = 0; i < 8; i++) {
                ull aa = dup2(a[i]);
#pragma unroll
                for (int j = 0; j < 4; j++) fma2(acc[i][j], aa, b2[j]);
            }
        }
        if (hasNext) {
            int ns = stage ^ 1;
            As[ns][acol + 0][arow] = av.x;
            As[ns][acol + 1][arow] = av.y;
            As[ns][acol + 2][arow] = av.z;
            As[ns][acol + 3][arow] = av.w;
            *(float4*)&Bs[ns][brow][bcol] = bv;
            __syncthreads();
            stage = ns;
        }
    }

    float bvals[8];
#pragma unroll
    for (int j = 0; j < 8; j++) bvals[j] = bias[bn + 8 * tx + j];

    if (QKV) {
        const int n0 = bn + 8 * tx;
        const int which = n0 >> 10;
        const int cc = n0 & 1023;
        const int h = cc >> 6, d0 = cc & 63;
        float* dstBase = (which == 0) ? g_q : ((which == 1) ? g_k : g_v);
#pragma unroll
        for (int i = 0; i < 8; i++) {
            int m = bm + 8 * ty + i;
            int b = m >> 11, t = m & 2047;
            float* crow = dstBase + ((size_t)((b * H_ + h) * T_ + t)) * D_ + d0;
            float2 p0 = unpack2(acc[i][0]), p1 = unpack2(acc[i][1]);
            float2 p2 = unpack2(acc[i][2]), p3 = unpack2(acc[i][3]);
            *(float4*)crow = make_float4(p0.x + bvals[0], p0.y + bvals[1],
                                         p1.x + bvals[2], p1.y + bvals[3]);
            *(float4*)(crow + 4) = make_float4(p2.x + bvals[4], p2.y + bvals[5],
                                               p3.x + bvals[6], p3.y + bvals[7]);
        }
    } else {
#pragma unroll
        for (int i = 0; i < 8; i++) {
            float* crow = C + (size_t)(bm + 8 * ty + i) * N + bn + 8 * tx;
            float2 p0 = unpack2(acc[i][0]), p1 = unpack2(acc[i][1]);
            float2 p2 = unpack2(acc[i][2]), p3 = unpack2(acc[i][3]);
            *(float4*)crow = make_float4(p0.x + bvals[0], p0.y + bvals[1],
                                         p1.x + bvals[2], p1.y + bvals[3]);
            *(float4*)(crow + 4) = make_float4(p2.x + bvals[4], p2.y + bvals[5],
                                               p3.x + bvals[6], p3.y + bvals[7]);
        }
    }
}

// ---------------- accurate cos for x in [0, ~6500], fast-math-proof ----------------
__device__ __forceinline__ float cos_cw(float x) {
    float k = rintf(x * 0.31830988618379067f);               // x / pi
    float r = fmaf(-k, 3.14159274101257324f, x);             // hi part of pi
    r = fmaf(-k, -8.74227765734758e-8f, r);                  // lo part
    float r2 = r * r;
    float p = -2.75573192e-7f;
    p = fmaf(p, r2, 2.48015873e-5f);
    p = fmaf(p, r2, -1.38888889e-3f);
    p = fmaf(p, r2, 4.16666667e-2f);
    p = fmaf(p, r2, -0.5f);
    p = fmaf(p, r2, 1.0f);
    int ki = (int)k;
    return (ki & 1) ? -p : p;
}

// ---------------- per-head mask weight table: W[h][rel] = mask_pos * wave ----------------
__global__ void mask_table_kernel(const float* __restrict__ sp, const float* __restrict__ pw,
                                  const float* __restrict__ rw) {
    const int h = blockIdx.x;
    float span = 2048.0f / (1.0f + expf(-sp[h]));
    float period = 2.0f + 2.0f / (1.0f + expf(-pw[h]));
    float amp = period * 0.25f;
    float ratio = -0.25f + 0.5f / (1.0f + expf(-rw[h]));
    float offset = period * ratio;
    for (int rel = threadIdx.x; rel < T_; rel += blockDim.x) {
        float relf = (float)rel;
        float mp = ((32.0f - relf) + span) * 0.03125f;          // (R - rel + span)/R
        mp = fminf(fmaxf(mp, 0.0f), 1.0f);
        float arg = __fdiv_rn(__fmul_rn(6.2831855f, relf), period);
        float wave = (0.5f * (cos_cw(arg) + 1.0f)) * amp + 0.5f + offset;
        wave = fminf(fmaxf(wave, 0.0f), 1.0f);
        g_W[h * T_ + rel] = mp * wave;
    }
}

// ---------------- fused masked flash attention ----------------
// grid (T/128, H, B), 256 threads, Br=128, Bc=64, D=64.
// Per thread: 8 rows x 4 cols. Swizzled smem to kill store bank conflicts.
__global__ __launch_bounds__(256)
void flash_kernel(const float* __restrict__ sp, float* __restrict__ y) {
    extern __shared__ float smf[];
    float* Qs = smf;                              // [64 d][132 i]   (swizzled i)
    float* Ks = smf + 64 * 132;                   // [64 d][68 j]    (swizzled j)
    float* Vs = smf + 64 * 132 + 64 * 68;         // [64 j][68 d]
    float* Ps = smf + 64 * 132 + 2 * 64 * 68;     // [64 j][132 i]   (swizzled i)
    // total: 8448 + 4352 + 4352 + 8448 = 25600 floats = 102,400 B

    const int iTile = blockIdx.x, h = blockIdx.y, b = blockIdx.z;
    const int tid = threadIdx.x, tx = tid & 15, ty = tid >> 4;
    const int i0 = iTile * 128;

    float span = 2048.0f / (1.0f + expf(-sp[h]));
    float cutoff = span + 32.0f;
    const float* Wt = g_W + h * T_;

    const float* qg = g_q + ((size_t)(b * H_ + h) * T_ + i0) * D_;
    const float* kgBase = g_k + (size_t)(b * H_ + h) * T_ * D_;
    const float* vgBase = g_v + (size_t)(b * H_ + h) * T_ * D_;

    const int ldr = tid >> 4;             // row base (16 rows per rep)
    const int ldd = (tid & 15) << 2;      // d4 (also 4-col group in K/V tiles)

    // load Q tile (128 rows), transposed + swizzled into smem
#pragma unroll
    for (int rep = 0; rep < 8; rep++) {
        int r = rep * 16 + ldr;
        float4 qv = *(const float4*)&qg[r * 64 + ldd];
        Qs[(ldd + 0) * 132 + (r ^ sw4(ldd + 0))] = qv.x;
        Qs[(ldd + 1) * 132 + (r ^ sw4(ldd + 1))] = qv.y;
        Qs[(ldd + 2) * 132 + (r ^ sw4(ldd + 2))] = qv.z;
        Qs[(ldd + 3) * 132 + (r ^ sw4(ldd + 3))] = qv.w;
    }

    float m_i[8], l_i[8];
    ull O2[8][2];
#pragma unroll
    for (int r = 0; r < 8; r++) {
        m_i[r] = -1e30f; l_i[r] = 0.0f;
        O2[r][0] = 0ull; O2[r][1] = 0ull;
    }

    // skip j-tiles where rel > cutoff for every element (mask_pos == 0 exactly)
    int v0 = i0 - (int)cutoff - 63;
    int jStart = (v0 > 0) ? (v0 >> 6) : 0;
    const int jEnd = (i0 + 127) >> 6;        // = 2*iTile + 1

    // prefetch first K/V tile into registers
    float4 kreg[4], vreg[4];
    {
        const int j0 = jStart * 64;
#pragma unroll
        for (int rep = 0; rep < 4; rep++) {
            int r = rep * 16 + ldr;
            kreg[rep] = *(const float4*)&kgBase[(size_t)(j0 + r) * 64 + ldd];
            vreg[rep] = *(const float4*)&vgBase[(size_t)(j0 + r) * 64 + ldd];
        }
    }

    for (int jt = jStart; jt <= jEnd; jt++) {
        const int j0 = jt * 64;
        __syncthreads();   // previous tile's consumers done with Ks/Vs/Ps
#pragma unroll
        for (int rep = 0; rep < 4; rep++) {
            int r = rep * 16 + ldr;
            Ks[(ldd + 0) * 68 + (r ^ sw4(ldd + 0))] = kreg[rep].x;
            Ks[(ldd + 1) * 68 + (r ^ sw4(ldd + 1))] = kreg[rep].y;
            Ks[(ldd + 2) * 68 + (r ^ sw4(ldd + 2))] = kreg[rep].z;
            Ks[(ldd + 3) * 68 + (r ^ sw4(ldd + 3))] = kreg[rep].w;
            *(float4*)&Vs[r * 68 + ldd] = vreg[rep];
        }
        __syncthreads();

        // prefetch next K/V tile — LDG latency overlaps with compute below
        if (jt < jEnd) {
            const int jn = j0 + 64;
#pragma unroll
            for (int rep = 0; rep < 4; rep++) {
                int r = rep * 16 + ldr;
                kreg[rep] = *(const float4*)&kgBase[(size_t)(jn + r) * 64 + ldd];
                vreg[rep] = *(const float4*)&vgBase[(size_t)(jn + r) * 64 + ldd];
            }
        }

        // S = Q K^T  (8x4 per thread, packed over the tx/col dim)
        ull s2[8][2];
#pragma unroll
        for (int r = 0; r < 8; r++) { s2[r][0] = 0ull; s2[r][1] = 0ull; }
#pragma unroll 4
        for (int d = 0; d < 64; d++) {
            const int sw = sw4(d);
            float a[8];
            *(float4*)&a[0] = *(const float4*)&Qs[d * 132 + ((8 * ty) ^ sw)];
            *(float4*)&a[4] = *(const float4*)&Qs[d * 132 + ((8 * ty + 4) ^ sw)];
            ulonglong2 kp = *(const ulonglong2*)&Ks[d * 68 + ((4 * tx) ^ sw)];
#pragma unroll
            for (int r = 0; r < 8; r++) {
                ull aa = dup2(a[r]);
                fma2(s2[r][0], aa, kp.x);
                fma2(s2[r][1], aa, kp.y);
            }
        }

        // mask (table lookup) + causal + local row max
        float p[8][4], mloc[8];
#pragma unroll
        for (int r = 0; r < 8; r++) {
            float2 u0 = unpack2(s2[r][0]), u1 = unpack2(s2[r][1]);
            float s[4] = {u0.x, u0.y, u1.x, u1.y};
            int ig = i0 + 8 * ty + r;
            mloc[r] = -1e30f;
#pragma unroll
            for (int c = 0; c < 4; c++) {
                int jg = j0 + 4 * tx + c;
                int reli = ig - jg;
                if (reli < 0) {
                    s[c] = -1e30f; p[r][c] = 0.0f;
                } else {
                    float sv = s[c] * 0.125f;
                    s[c] = sv;
                    p[r][c] = __ldg(&Wt[reli]);
                    mloc[r] = fmaxf(mloc[r], sv);
                }
            }
            // stash scaled s back into s2 (packed) to keep registers tight
            s2[r][0] = (ull)__float_as_uint(s[0]) | ((ull)__float_as_uint(s[1]) << 32);
            s2[r][1] = (ull)__float_as_uint(s[2]) | ((ull)__float_as_uint(s[3]) << 32);
        }
        // reduce row max over the 16 tx lanes (same-ty lanes are xor 1,2,4,8 apart)
#pragma unroll
        for (int off = 1; off < 16; off <<= 1)
#pragma unroll
            for (int r = 0; r < 8; r++)
                mloc[r] = fmaxf(mloc[r], __shfl_xor_sync(0xffffffffu, mloc[r], off));

        float lloc[8], alpha[8];
#pragma unroll
        for (int r = 0; r < 8; r++) {
            float mn = fmaxf(m_i[r], mloc[r]);
            alpha[r] = __expf(m_i[r] - mn);
            m_i[r] = mn;
            float2 u0 = unpack2(s2[r][0]), u1 = unpack2(s2[r][1]);
            float s[4] = {u0.x, u0.y, u1.x, u1.y};
            lloc[r] = 0.0f;
#pragma unroll
            for (int c = 0; c < 4; c++) {
                p[r][c] *= __expf(s[c] - mn);
                lloc[r] += p[r][c];
            }
        }
#pragma unroll
        for (int off = 1; off < 16; off <<= 1)
#pragma unroll
            for (int r = 0; r < 8; r++)
                lloc[r] += __shfl_xor_sync(0xffffffffu, lloc[r], off);
#pragma unroll
        for (int r = 0; r < 8; r++) {
            l_i[r] = l_i[r] * alpha[r] + lloc[r];
            ull aa = dup2(alpha[r]);
            mul2(O2[r][0], O2[r][0], aa);
            mul2(O2[r][1], O2[r][1], aa);
        }

        // store P transposed [j][i], swizzled
#pragma unroll
        for (int c = 0; c < 4; c++) {
            const int jj = 4 * tx + c;
            const int sw = sw4(jj);
#pragma unroll
            for (int r = 0; r < 8; r++)
                Ps[jj * 132 + ((8 * ty + r) ^ sw)] = p[r][c];
        }
        __syncthreads();

        // O += P @ V  (packed over the tx/col dim)
#pragma unroll 4
        for (int j = 0; j < 64; j++) {
            const int sw = sw4(j);
            float a[8];
            *(float4*)&a[0] = *(const float4*)&Ps[j * 132 + ((8 * ty) ^ sw)];
            *(float4*)&a[4] = *(const float4*)&Ps[j * 132 + ((8 * ty + 4) ^ sw)];
            ulonglong2 vp = *(const ulonglong2*)&Vs[j * 68 + 4 * tx];
#pragma unroll
            for (int r = 0; r < 8; r++) {
                ull aa = dup2(a[r]);
                fma2(O2[r][0], aa, vp.x);
                fma2(O2[r][1], aa, vp.y);
            }
        }
    }

    // normalize and write y [B,T,C] with C = h*64 + d
#pragma unroll
    for (int r = 0; r < 8; r++) {
        int ig = i0 + 8 * ty + r;
        float inv = 1.0f / l_i[r];
        float2 o0 = unpack2(O2[r][0]), o1 = unpack2(O2[r][1]);
        float4 outv = make_float4(o0.x * inv, o0.y * inv, o1.x * inv, o1.y * inv);
        *(float4*)&y[(size_t)(b * T_ + ig) * C_ + h * D_ + 4 * tx] = outv;
    }
}

// ---------------- span loss (scalar) ----------------
__global__ void span_loss_kernel(const float* __restrict__ sp, const float* __restrict__ pw,
                                 const float* __restrict__ rw, float* __restrict__ out) {
    int hh = threadIdx.x;
    float val = 0.0f;
    if (hh < H_) {
        float span = 2048.0f / (1.0f + expf(-sp[hh]));
        float period = 2.0f + 2.0f / (1.0f + expf(-pw[hh]));
        float ratio = -0.25f + 0.5f / (1.0f + expf(-rw[hh]));
        float lt = 1.0f / period + 2.0f * ratio - 0.25f + 0.5f;
        val = (span + 32.0f) * lt;
    }
#pragma unroll
    for (int off = 16; off > 0; off >>= 1)
        val += __shfl_xor_sync(0xffffffffu, val, off);
    if (hh == 0) out[0] = 2e-6f * val / 16.0f;
}

// ---------------- launch ----------------
extern "C" void kernel_launch(void* const* d_in, const int* in_sizes, int n_in,
                              void* d_out, int out_size) {
    (void)in_sizes; (void)n_in;
    const float* x      = (const float*)d_in[0];
    const float* w_attn = (const float*)d_in[1];
    const float* b_attn = (const float*)d_in[2];
    const float* w_proj = (const float*)d_in[3];
    const float* b_proj = (const float*)d_in[4];
    const float* sp     = (const float*)d_in[5];
    const float* pw     = (const float*)d_in[6];
    const float* rw     = (const float*)d_in[7];
    float* out = (float*)d_out;

    float* y_ptr;
    cudaGetSymbolAddress((void**)&y_ptr, g_y);

    // per-head mask weight table (tiny)
    mask_table_kernel<<<H_, 256>>>(sp, pw, rw);
    // qkv = x @ w_attn + b_attn, scattered directly into g_q/g_k/g_v [B,H,T,D]
    gemm_bias_kernel<true><<<dim3(24, 32), 256>>>(x, w_attn, b_attn, nullptr, 4096, 3072, 1024);
    // fused masked attention (Br=128, Bc=64)
    const size_t FSM = (size_t)(64 * 132 + 2 * 64 * 68 + 64 * 132) * sizeof(float);  // 102,400 B
    cudaFuncSetAttribute(flash_kernel, cudaFuncAttributeMaxDynamicSharedMemorySize, (int)FSM);
    flash_kernel<<<dim3(16, 16, 2), 256, FSM>>>(sp, y_ptr);
    // y = y_att @ w_proj + b_proj  (written directly to d_out)
    gemm_bias_kernel<false><<<dim3(8, 32), 256>>>(y_ptr, w_proj, b_proj, out, 4096, 1024, 1024);
    // span loss -> last output element
    span_loss_kernel<<<1, 32>>>(sp, pw, rw, out + (size_t)out_size - 1);
}

// round 6
// speedup vs baseline: 1.1017x; 1.1017x over previous
#include <cuda_runtime.h>

#define B_ 2
#define T_ 2048
#define H_ 16
#define D_ 64
#define C_ 1024

// ---------------- scratch (no cudaMalloc allowed) ----------------
__device__ float g_q[(size_t)B_ * H_ * T_ * D_];       // [B,H,T,D]
__device__ float g_k[(size_t)B_ * H_ * T_ * D_];
__device__ float g_v[(size_t)B_ * H_ * T_ * D_];
__device__ float g_y[(size_t)B_ * T_ * C_];            // attention out [B,T,C]
__device__ float g_W[H_ * T_];                          // mask weight table [H][rel]

// ---------------- packed f32x2 helpers ----------------
typedef unsigned long long ull;

__device__ __forceinline__ ull dup2(float x) {
    ull r;
    asm("mov.b64 %0, {%1, %1};" : "=l"(r) : "f"(x));
    return r;
}
__device__ __forceinline__ void fma2(ull& d, ull a, ull b) {
    asm("fma.rn.f32x2 %0, %1, %2, %0;" : "+l"(d) : "l"(a), "l"(b));
}
__device__ __forceinline__ void mul2(ull& d, ull a, ull b) {
    asm("mul.rn.f32x2 %0, %1, %2;" : "=l"(d) : "l"(a), "l"(b));
}
__device__ __forceinline__ float2 unpack2(ull v) {
    float2 f;
    f.x = __uint_as_float((unsigned)v);
    f.y = __uint_as_float((unsigned)(v >> 32));
    return f;
}

// bank-conflict swizzle: XOR the minor index (4-float granular, keeps 16B align)
__device__ __forceinline__ int sw4(int major) { return ((major >> 2) & 7) << 2; }

// ---------------- GEMM: C[M,N] = A[M,K] @ B[K,N] + bias[N] ----------------
// 128x128 tile, BK=8, 256 threads, 8x8 microtile, f32x2 packed FMA,
// 2-stage smem double buffering.
// B-frag layout: thread covers cols {4tx..4tx+3} U {64+4tx..64+4tx+3}
//   -> quarter-warp LDS word offsets stride 4: conflict-free
//   (old 8*tx layout was 2-way bank conflicted on every B-frag load).
// QKV=true: scatter output into g_q/g_k/g_v as [B,H,T,D] (N=3072 layout).
template<bool QKV>
__global__ __launch_bounds__(256, 2)
void gemm_bias_kernel(const float* __restrict__ A, const float* __restrict__ Bm,
                      const float* __restrict__ bias, float* __restrict__ C,
                      int M, int N, int K) {
    __shared__ float As[2][8][132];   // [stage][k][m] transposed, padded
    __shared__ float Bs[2][8][128];   // [stage][k][n]
    const int tid = threadIdx.x;
    const int tx = tid & 15, ty = tid >> 4;
    const int bm = blockIdx.y * 128, bn = blockIdx.x * 128;
    const int arow = tid >> 1, acol = (tid & 1) * 4;
    const int brow = tid >> 5, bcol = (tid & 31) * 4;

    ull acc[8][4];   // [row][pair]: pairs 0,1 = cols 4tx..+3 ; pairs 2,3 = cols 64+4tx..+3
#pragma unroll
    for (int i = 0; i < 8; i++)
#pragma unroll
        for (int j = 0; j < 4; j++) acc[i][j] = 0ull;

    const float* aptr = A + (size_t)(bm + arow) * K + acol;
    const float* bptr = Bm + (size_t)brow * N + bn + bcol;

    float4 av = *(const float4*)(aptr);
    float4 bv = *(const float4*)(bptr);
    As[0][acol + 0][arow] = av.x;
    As[0][acol + 1][arow] = av.y;
    As[0][acol + 2][arow] = av.z;
    As[0][acol + 3][arow] = av.w;
    *(float4*)&Bs[0][brow][bcol] = bv;
    __syncthreads();

    int stage = 0;
    for (int k0 = 0; k0 < K; k0 += 8) {
        const bool hasNext = (k0 + 8) < K;
        if (hasNext) {
            av = *(const float4*)(aptr + k0 + 8);
            bv = *(const float4*)(bptr + (size_t)(k0 + 8) * N);
        }
#pragma unroll
        for (int kk = 0; kk < 8; kk++) {
            float a[8];
            *(float4*)&a[0] = *(const float4*)&As[stage][kk][8 * ty];
            *(float4*)&a[4] = *(const float4*)&As[stage][kk][8 * ty + 4];
            ull b2[4];
            ulonglong2 bl0 = *(const ulonglong2*)&Bs[stage][kk][4 * tx];        // conflict-free
            ulonglong2 bl1 = *(const ulonglong2*)&Bs[stage][kk][64 + 4 * tx];   // conflict-free
            b2[0] = bl0.x; b2[1] = bl0.y; b2[2] = bl1.x; b2[3] = bl1.y;
#pragma unroll
            for (int i = 0; i < 8; i++) {
                ull aa = dup2(a[i]);
#pragma unroll
                for (int j = 0; j < 4; j++) fma2(acc[i][j], aa, b2[j]);
            }
        }
        if (hasNext) {
            int ns = stage ^ 1;
            As[ns][acol + 0][arow] = av.x;
            As[ns][acol + 1][arow] = av.y;
            As[ns][acol + 2][arow] = av.z;
            As[ns][acol + 3][arow] = av.w;
            *(float4*)&Bs[ns][brow][bcol] = bv;
            __syncthreads();
            stage = ns;
        }
    }

    const int g0 = bn + 4 * tx;          // group0 base col
    const int g1 = g0 + 64;              // group1 base col
    float bvals[8];
#pragma unroll
    for (int j = 0; j < 4; j++) bvals[j] = __ldg(&bias[g0 + j]);
#pragma unroll
    for (int j = 0; j < 4; j++) bvals[4 + j] = __ldg(&bias[g1 + j]);

    if (QKV) {
        // independent scatter params per group (group1 may cross head/tensor bound)
        const int wh0 = g0 >> 10, cc0 = g0 & 1023, h0 = cc0 >> 6, d00 = cc0 & 63;
        const int wh1 = g1 >> 10, cc1 = g1 & 1023, h1 = cc1 >> 6, d01 = cc1 & 63;
        float* base0 = (wh0 == 0) ? g_q : ((wh0 == 1) ? g_k : g_v);
        float* base1 = (wh1 == 0) ? g_q : ((wh1 == 1) ? g_k : g_v);
#pragma unroll
        for (int i = 0; i < 8; i++) {
            int m = bm + 8 * ty + i;
            int b = m >> 11, t = m & 2047;
            float2 p0 = unpack2(acc[i][0]), p1 = unpack2(acc[i][1]);
            float2 p2 = unpack2(acc[i][2]), p3 = unpack2(acc[i][3]);
            float* r0 = base0 + ((size_t)((b * H_ + h0) * T_ + t)) * D_ + d00;
            float* r1 = base1 + ((size_t)((b * H_ + h1) * T_ + t)) * D_ + d01;
            *(float4*)r0 = make_float4(p0.x + bvals[0], p0.y + bvals[1],
                                       p1.x + bvals[2], p1.y + bvals[3]);
            *(float4*)r1 = make_float4(p2.x + bvals[4], p2.y + bvals[5],
                                       p3.x + bvals[6], p3.y + bvals[7]);
        }
    } else {
#pragma unroll
        for (int i = 0; i < 8; i++) {
            float* crow = C + (size_t)(bm + 8 * ty + i) * N;
            float2 p0 = unpack2(acc[i][0]), p1 = unpack2(acc[i][1]);
            float2 p2 = unpack2(acc[i][2]), p3 = unpack2(acc[i][3]);
            *(float4*)(crow + g0) = make_float4(p0.x + bvals[0], p0.y + bvals[1],
                                                p1.x + bvals[2], p1.y + bvals[3]);
            *(float4*)(crow + g1) = make_float4(p2.x + bvals[4], p2.y + bvals[5],
                                                p3.x + bvals[6], p3.y + bvals[7]);
        }
    }
}

// ---------------- accurate cos for x in [0, ~6500], fast-math-proof ----------------
__device__ __forceinline__ float cos_cw(float x) {
    float k = rintf(x * 0.31830988618379067f);               // x / pi
    float r = fmaf(-k, 3.14159274101257324f, x);             // hi part of pi
    r = fmaf(-k, -8.74227765734758e-8f, r);                  // lo part
    float r2 = r * r;
    float p = -2.75573192e-7f;
    p = fmaf(p, r2, 2.48015873e-5f);
    p = fmaf(p, r2, -1.38888889e-3f);
    p = fmaf(p, r2, 4.16666667e-2f);
    p = fmaf(p, r2, -0.5f);
    p = fmaf(p, r2, 1.0f);
    int ki = (int)k;
    return (ki & 1) ? -p : p;
}

// ---------------- per-head mask weight table: W[h][rel] = mask_pos * wave ----------------
__global__ void mask_table_kernel(const float* __restrict__ sp, const float* __restrict__ pw,
                                  const float* __restrict__ rw) {
    const int h = blockIdx.x;
    float span = 2048.0f / (1.0f + expf(-sp[h]));
    float period = 2.0f + 2.0f / (1.0f + expf(-pw[h]));
    float amp = period * 0.25f;
    float ratio = -0.25f + 0.5f / (1.0f + expf(-rw[h]));
    float offset = period * ratio;
    for (int rel = threadIdx.x; rel < T_; rel += blockDim.x) {
        float relf = (float)rel;
        float mp = ((32.0f - relf) + span) * 0.03125f;          // (R - rel + span)/R
        mp = fminf(fmaxf(mp, 0.0f), 1.0f);
        float arg = __fdiv_rn(__fmul_rn(6.2831855f, relf), period);
        float wave = (0.5f * (cos_cw(arg) + 1.0f)) * amp + 0.5f + offset;
        wave = fminf(fmaxf(wave, 0.0f), 1.0f);
        g_W[h * T_ + rel] = mp * wave;
    }
}

// ---------------- fused masked flash attention ----------------
// grid (T/128, H, B), 256 threads, Br=128, Bc=64, D=64.
// Per thread: 8 rows x 4 cols. Swizzled smem. Heavy tiles launch first.
__global__ __launch_bounds__(256)
void flash_kernel(const float* __restrict__ sp, float* __restrict__ y) {
    extern __shared__ float smf[];
    float* Qs = smf;                              // [64 d][132 i]   (swizzled i)
    float* Ks = smf + 64 * 132;                   // [64 d][68 j]    (swizzled j)
    float* Vs = smf + 64 * 132 + 64 * 68;         // [64 j][68 d]
    float* Ps = smf + 64 * 132 + 2 * 64 * 68;     // [64 j][132 i]   (swizzled i)

    const int iTile = (int)gridDim.x - 1 - (int)blockIdx.x;   // heavy first
    const int h = blockIdx.y, b = blockIdx.z;
    const int tid = threadIdx.x, tx = tid & 15, ty = tid >> 4;
    const int i0 = iTile * 128;

    float span = 2048.0f / (1.0f + expf(-sp[h]));
    float cutoff = span + 32.0f;
    const float* Wt = g_W + h * T_;

    const float* qg = g_q + ((size_t)(b * H_ + h) * T_ + i0) * D_;
    const float* kgBase = g_k + (size_t)(b * H_ + h) * T_ * D_;
    const float* vgBase = g_v + (size_t)(b * H_ + h) * T_ * D_;

    const int ldr = tid >> 4;             // row base (16 rows per rep)
    const int ldd = (tid & 15) << 2;      // d4

    // load Q tile (128 rows), transposed + swizzled into smem
#pragma unroll
    for (int rep = 0; rep < 8; rep++) {
        int r = rep * 16 + ldr;
        float4 qv = *(const float4*)&qg[r * 64 + ldd];
        Qs[(ldd + 0) * 132 + (r ^ sw4(ldd + 0))] = qv.x;
        Qs[(ldd + 1) * 132 + (r ^ sw4(ldd + 1))] = qv.y;
        Qs[(ldd + 2) * 132 + (r ^ sw4(ldd + 2))] = qv.z;
        Qs[(ldd + 3) * 132 + (r ^ sw4(ldd + 3))] = qv.w;
    }

    float m_i[8], l_i[8];
    ull O2[8][2];
#pragma unroll
    for (int r = 0; r < 8; r++) {
        m_i[r] = -1e30f; l_i[r] = 0.0f;
        O2[r][0] = 0ull; O2[r][1] = 0ull;
    }

    // skip j-tiles where rel > cutoff for every element (mask_pos == 0 exactly)
    int v0 = i0 - (int)cutoff - 63;
    int jStart = (v0 > 0) ? (v0 >> 6) : 0;
    const int jEnd = (i0 + 127) >> 6;

    // prefetch first K/V tile into registers
    float4 kreg[4], vreg[4];
    {
        const int j0 = jStart * 64;
#pragma unroll
        for (int rep = 0; rep < 4; rep++) {
            int r = rep * 16 + ldr;
            kreg[rep] = *(const float4*)&kgBase[(size_t)(j0 + r) * 64 + ldd];
            vreg[rep] = *(const float4*)&vgBase[(size_t)(j0 + r) * 64 + ldd];
        }
    }

    for (int jt = jStart; jt <= jEnd; jt++) {
        const int j0 = jt * 64;
        __syncthreads();
#pragma unroll
        for (int rep = 0; rep < 4; rep++) {
            int r = rep * 16 + ldr;
            Ks[(ldd + 0) * 68 + (r ^ sw4(ldd + 0))] = kreg[rep].x;
            Ks[(ldd + 1) * 68 + (r ^ sw4(ldd + 1))] = kreg[rep].y;
            Ks[(ldd + 2) * 68 + (r ^ sw4(ldd + 2))] = kreg[rep].z;
            Ks[(ldd + 3) * 68 + (r ^ sw4(ldd + 3))] = kreg[rep].w;
            *(float4*)&Vs[r * 68 + ldd] = vreg[rep];
        }
        __syncthreads();

        if (jt < jEnd) {
            const int jn = j0 + 64;
#pragma unroll
            for (int rep = 0; rep < 4; rep++) {
                int r = rep * 16 + ldr;
                kreg[rep] = *(const float4*)&kgBase[(size_t)(jn + r) * 64 + ldd];
                vreg[rep] = *(const float4*)&vgBase[(size_t)(jn + r) * 64 + ldd];
            }
        }

        // S = Q K^T  (8x4 per thread, packed over the tx/col dim)
        ull s2[8][2];
#pragma unroll
        for (int r = 0; r < 8; r++) { s2[r][0] = 0ull; s2[r][1] = 0ull; }
#pragma unroll 4
        for (int d = 0; d < 64; d++) {
            const int sw = sw4(d);
            float a[8];
            *(float4*)&a[0] = *(const float4*)&Qs[d * 132 + ((8 * ty) ^ sw)];
            *(float4*)&a[4] = *(const float4*)&Qs[d * 132 + ((8 * ty + 4) ^ sw)];
            ulonglong2 kp = *(const ulonglong2*)&Ks[d * 68 + ((4 * tx) ^ sw)];
#pragma unroll
            for (int r = 0; r < 8; r++) {
                ull aa = dup2(a[r]);
                fma2(s2[r][0], aa, kp.x);
                fma2(s2[r][1], aa, kp.y);
            }
        }

        // mask (table lookup) + causal + local row max
        float p[8][4], mloc[8];
#pragma unroll
        for (int r = 0; r < 8; r++) {
            float2 u0 = unpack2(s2[r][0]), u1 = unpack2(s2[r][1]);
            float s[4] = {u0.x, u0.y, u1.x, u1.y};
            int ig = i0 + 8 * ty + r;
            mloc[r] = -1e30f;
#pragma unroll
            for (int c = 0; c < 4; c++) {
                int jg = j0 + 4 * tx + c;
                int reli = ig - jg;
                if (reli < 0) {
                    s[c] = -1e30f; p[r][c] = 0.0f;
                } else {
                    float sv = s[c] * 0.125f;
                    s[c] = sv;
                    p[r][c] = __ldg(&Wt[reli]);
                    mloc[r] = fmaxf(mloc[r], sv);
                }
            }
            s2[r][0] = (ull)__float_as_uint(s[0]) | ((ull)__float_as_uint(s[1]) << 32);
            s2[r][1] = (ull)__float_as_uint(s[2]) | ((ull)__float_as_uint(s[3]) << 32);
        }
#pragma unroll
        for (int off = 1; off < 16; off <<= 1)
#pragma unroll
            for (int r = 0; r < 8; r++)
                mloc[r] = fmaxf(mloc[r], __shfl_xor_sync(0xffffffffu, mloc[r], off));

        float lloc[8], alpha[8];
#pragma unroll
        for (int r = 0; r < 8; r++) {
            float mn = fmaxf(m_i[r], mloc[r]);
            alpha[r] = __expf(m_i[r] - mn);
            m_i[r] = mn;
            float2 u0 = unpack2(s2[r][0]), u1 = unpack2(s2[r][1]);
            float s[4] = {u0.x, u0.y, u1.x, u1.y};
            lloc[r] = 0.0f;
#pragma unroll
            for (int c = 0; c < 4; c++) {
                p[r][c] *= __expf(s[c] - mn);
                lloc[r] += p[r][c];
            }
        }
#pragma unroll
        for (int off = 1; off < 16; off <<= 1)
#pragma unroll
            for (int r = 0; r < 8; r++)
                lloc[r] += __shfl_xor_sync(0xffffffffu, lloc[r], off);
#pragma unroll
        for (int r = 0; r < 8; r++) {
            l_i[r] = l_i[r] * alpha[r] + lloc[r];
            ull aa = dup2(alpha[r]);
            mul2(O2[r][0], O2[r][0], aa);
            mul2(O2[r][1], O2[r][1], aa);
        }

        // store P transposed [j][i], swizzled
#pragma unroll
        for (int c = 0; c < 4; c++) {
            const int jj = 4 * tx + c;
            const int sw = sw4(jj);
#pragma unroll
            for (int r = 0; r < 8; r++)
                Ps[jj * 132 + ((8 * ty + r) ^ sw)] = p[r][c];
        }
        __syncthreads();

        // O += P @ V  (packed over the tx/col dim)
#pragma unroll 4
        for (int j = 0; j < 64; j++) {
            const int sw = sw4(j);
            float a[8];
            *(float4*)&a[0] = *(const float4*)&Ps[j * 132 + ((8 * ty) ^ sw)];
            *(float4*)&a[4] = *(const float4*)&Ps[j * 132 + ((8 * ty + 4) ^ sw)];
            ulonglong2 vp = *(const ulonglong2*)&Vs[j * 68 + 4 * tx];
#pragma unroll
            for (int r = 0; r < 8; r++) {
                ull aa = dup2(a[r]);
                fma2(O2[r][0], aa, vp.x);
                fma2(O2[r][1], aa, vp.y);
            }
        }
    }

    // normalize and write y [B,T,C] with C = h*64 + d
#pragma unroll
    for (int r = 0; r < 8; r++) {
        int ig = i0 + 8 * ty + r;
        float inv = 1.0f / l_i[r];
        float2 o0 = unpack2(O2[r][0]), o1 = unpack2(O2[r][1]);
        float4 outv = make_float4(o0.x * inv, o0.y * inv, o1.x * inv, o1.y * inv);
        *(float4*)&y[(size_t)(b * T_ + ig) * C_ + h * D_ + 4 * tx] = outv;
    }
}

// ---------------- span loss (scalar) ----------------
__global__ void span_loss_kernel(const float* __restrict__ sp, const float* __restrict__ pw,
                                 const float* __restrict__ rw, float* __restrict__ out) {
    int hh = threadIdx.x;
    float val = 0.0f;
    if (hh < H_) {
        float span = 2048.0f / (1.0f + expf(-sp[hh]));
        float period = 2.0f + 2.0f / (1.0f + expf(-pw[hh]));
        float ratio = -0.25f + 0.5f / (1.0f + expf(-rw[hh]));
        float lt = 1.0f / period + 2.0f * ratio - 0.25f + 0.5f;
        val = (span + 32.0f) * lt;
    }
#pragma unroll
    for (int off = 16; off > 0; off >>= 1)
        val += __shfl_xor_sync(0xffffffffu, val, off);
    if (hh == 0) out[0] = 2e-6f * val / 16.0f;
}

// ---------------- launch ----------------
extern "C" void kernel_launch(void* const* d_in, const int* in_sizes, int n_in,
                              void* d_out, int out_size) {
    (void)in_sizes; (void)n_in;
    const float* x      = (const float*)d_in[0];
    const float* w_attn = (const float*)d_in[1];
    const float* b_attn = (const float*)d_in[2];
    const float* w_proj = (const float*)d_in[3];
    const float* b_proj = (const float*)d_in[4];
    const float* sp     = (const float*)d_in[5];
    const float* pw     = (const float*)d_in[6];
    const float* rw     = (const float*)d_in[7];
    float* out = (float*)d_out;

    float* y_ptr;
    cudaGetSymbolAddress((void**)&y_ptr, g_y);

    // per-head mask weight table (tiny)
    mask_table_kernel<<<H_, 256>>>(sp, pw, rw);
    // qkv = x @ w_attn + b_attn, scattered directly into g_q/g_k/g_v [B,H,T,D]
    gemm_bias_kernel<true><<<dim3(24, 32), 256>>>(x, w_attn, b_attn, nullptr, 4096, 3072, 1024);
    // fused masked attention (Br=128, Bc=64)
    const size_t FSM = (size_t)(64 * 132 + 2 * 64 * 68 + 64 * 132) * sizeof(float);  // 102,400 B
    cudaFuncSetAttribute(flash_kernel, cudaFuncAttributeMaxDynamicSharedMemorySize, (int)FSM);
    flash_kernel<<<dim3(16, 16, 2), 256, FSM>>>(sp, y_ptr);
    // y = y_att @ w_proj + b_proj  (written directly to d_out)
    gemm_bias_kernel<false><<<dim3(8, 32), 256>>>(y_ptr, w_proj, b_proj, out, 4096, 1024, 1024);
    // span loss -> last output element
    span_loss_kernel<<<1, 32>>>(sp, pw, rw, out + (size_t)out_size - 1);
}